// round 5
// baseline (speedup 1.0000x reference)
#include <cuda_runtime.h>
#include <cuda_bf16.h>
#include <cstdint>

#define NV 50000
#define NE 400000
#define CN 12500
#define NROWS 100000
#define NTILES 782      /* ceil(100000/128) */
#define BST 72          /* bf16 elems per smem row (64 data + 8 pad) */
#define PPB 98          /* preproc blocks */

typedef unsigned long long ull;

// ---------------- scratch (static device memory) ----------------
__device__ int   d_bar;
__device__ int   d_degcnt[NV];
__device__ float d_degF[NV];
__device__ int   d_rowptr[NV + 1];
__device__ int   d_cursor[NV];
__device__ float d_deginv[NV];
__device__ int   d_blocksums[128];
__device__ int2  d_sorted[NE];              // (end, val bits)
__device__ float d_z0[(size_t)NV * 128];    // [v][b*64+k]
__device__ float d_out0[(size_t)NV * 256];  // row (2v+b) * 128
__device__ float d_z1[(size_t)NV * 256];
__device__ float d_out1[(size_t)NV * 256];
// Pre-converted bf16 weight images, padded layout: ((chunk*2+half)*128 + n)*BST + k
__device__ uint4 d_Bimg0[(2 * 2 * 128 * BST * 2) / 16];   // L0: 2 chunks x {hi,lo}
__device__ uint4 d_Bimg1[(4 * 2 * 128 * BST * 2) / 16];   // L1: 4 chunks x {hi,lo}

// ---------------- helpers ----------------
__device__ __forceinline__ uint32_t smem_u32(const void* p) {
    uint32_t a;
    asm("{ .reg .u64 t; cvta.to.shared.u64 t, %1; cvt.u32.u64 %0, t; }" : "=r"(a) : "l"(p));
    return a;
}
__device__ __forceinline__ void ldmat4(uint32_t* r, uint32_t addr) {
    asm volatile("ldmatrix.sync.aligned.m8n8.x4.shared.b16 {%0,%1,%2,%3}, [%4];"
                 : "=r"(r[0]), "=r"(r[1]), "=r"(r[2]), "=r"(r[3]) : "r"(addr));
}
__device__ __forceinline__ void mma_bf16(float* d, const uint32_t* a, const uint32_t* b) {
    asm volatile("mma.sync.aligned.m16n8k16.row.col.f32.bf16.bf16.f32 "
                 "{%0,%1,%2,%3}, {%4,%5,%6,%7}, {%8,%9}, {%0,%1,%2,%3};"
                 : "+f"(d[0]), "+f"(d[1]), "+f"(d[2]), "+f"(d[3])
                 : "r"(a[0]), "r"(a[1]), "r"(a[2]), "r"(a[3]), "r"(b[0]), "r"(b[1]));
}
__device__ __forceinline__ float bfhi(float x) {
    return __bfloat162float(__float2bfloat16(x));
}
__device__ __forceinline__ unsigned short bfb(float x) {
    return __bfloat16_as_ushort(__float2bfloat16(x));
}

// software grid barrier (all PPB blocks co-resident by construction)
__device__ __forceinline__ void gbar(int target) {
    __syncthreads();
    __threadfence();
    if (threadIdx.x == 0) {
        atomicAdd(&d_bar, 1);
        while (atomicAdd(&d_bar, 0) < target) { }
    }
    __syncthreads();
    __threadfence();
}

// ---------------- k_init: zero scratch + barrier + build bf16 hi/lo weight images ----------------
__global__ void k_init(const float* __restrict__ W0s, const float* __restrict__ W0n,
                       const float* __restrict__ W1s, const float* __restrict__ W1n) {
    int gt = blockIdx.x * blockDim.x + threadIdx.x;
    int stride = gridDim.x * blockDim.x;
    if (gt == 0) d_bar = 0;
    for (int i = gt; i < NV; i += stride) {
        d_degcnt[i] = 0; d_degF[i] = 0.f; d_cursor[i] = 0;
    }
    // items: L0 = 2 chunks * 128 n * 64 k = 16384; L1 = 32768
    for (int it = gt; it < 49152; it += stride) {
        bool isL1 = it >= 16384;
        int loc = isL1 ? (it - 16384) : it;
        int c = loc >> 13;
        int rem = loc & 8191;
        int n = rem >> 6;
        int kk = rem & 63;
        int k = c * 64 + kk;
        int KH = isL1 ? 128 : 64;
        const float* W;
        if (isL1) W = (k < KH) ? W1s : (W1n - (size_t)KH * 128);
        else      W = (k < KH) ? W0s : (W0n - (size_t)KH * 128);
        float v = W[(size_t)k * 128 + n];
        float hi = bfhi(v);
        unsigned short* img = isL1 ? (unsigned short*)d_Bimg1 : (unsigned short*)d_Bimg0;
        img[((size_t)(c * 2 + 0) * 128 + n) * BST + kk] = bfb(v);
        img[((size_t)(c * 2 + 1) * 128 + n) * BST + kk] = bfb(v - hi);
    }
}

// ---------------- k_preproc: hist -> scan -> fixup -> CSR fill (one kernel, grid barriers) ----------------
__global__ void __launch_bounds__(512) k_preproc(const int* __restrict__ Es,
                                                 const int* __restrict__ Ee,
                                                 const float* __restrict__ adj,
                                                 const float* __restrict__ one) {
    __shared__ int s[512];
    const int NT = PPB * 512;
    int tid = threadIdx.x;
    int gt = blockIdx.x * 512 + tid;

    // phase 0: degree histogram
    for (int e = gt; e < NE; e += NT) {
        int src = Es[e];
        atomicAdd(&d_degcnt[src], 1);
        atomicAdd(&d_degF[src], one[e]);
    }
    gbar(PPB);

    // phase 1: per-block inclusive scan of degcnt
    int val = (gt < NV) ? d_degcnt[gt] : 0;
    s[tid] = val;
    __syncthreads();
    for (int off = 1; off < 512; off <<= 1) {
        int t = (tid >= off) ? s[tid - off] : 0;
        __syncthreads();
        s[tid] += t;
        __syncthreads();
    }
    if (gt < NV) d_rowptr[gt + 1] = s[tid];
    if (tid == 511) d_blocksums[blockIdx.x] = s[511];
    gbar(2 * PPB);

    // phase 2: redundant scan of block sums + fixup + deginv
    {
        s[tid] = (tid < PPB) ? d_blocksums[tid] : 0;
        __syncthreads();
        for (int off = 1; off < 512; off <<= 1) {
            int u = (tid >= off) ? s[tid - off] : 0;
            __syncthreads();
            s[tid] += u;
            __syncthreads();
        }
        int boff = (blockIdx.x > 0) ? s[blockIdx.x - 1] : 0;
        if (gt < NV) {
            d_rowptr[gt + 1] += boff;
            d_deginv[gt] = 1.0f / fmaxf(d_degF[gt], 1.0f);
        }
        if (gt == 0) d_rowptr[0] = 0;
    }
    gbar(3 * PPB);

    // phase 3: CSR fill
    for (int e = gt; e < NE; e += NT) {
        int src = Es[e];
        int p = atomicAdd(&d_cursor[src], 1);
        d_sorted[d_rowptr[src] + p] = make_int2(Ee[e], __float_as_int(adj[e]));
    }
}

// ---------------- aggregation: warp per node, float4 per lane ----------------
__global__ void __launch_bounds__(256) k_gather64(const float* __restrict__ x) {
    int v = blockIdx.x * 8 + (threadIdx.x >> 5);
    int lane = threadIdx.x & 31;
    int b = lane >> 4, k = (lane & 15) * 4;
    const float* xb = x + ((size_t)b * NV) * 64 + k;
    int i = d_rowptr[v], end = d_rowptr[v + 1];
    float4 acc = make_float4(0.f, 0.f, 0.f, 0.f);
    for (; i < end; i++) {
        int2 ev = d_sorted[i];
        float w = __int_as_float(ev.y);
        float4 f = *(const float4*)(xb + (size_t)ev.x * 64);
        acc.x = fmaf(w, f.x, acc.x);
        acc.y = fmaf(w, f.y, acc.y);
        acc.z = fmaf(w, f.z, acc.z);
        acc.w = fmaf(w, f.w, acc.w);
    }
    float di = d_deginv[v];
    acc.x *= di; acc.y *= di; acc.z *= di; acc.w *= di;
    *(float4*)(d_z0 + (size_t)v * 128 + lane * 4) = acc;
}

__global__ void __launch_bounds__(256) k_gather128() {
    int v = blockIdx.x * 8 + (threadIdx.x >> 5);
    int lane = threadIdx.x & 31;
    int i = d_rowptr[v], end = d_rowptr[v + 1];
    float4 a0 = make_float4(0.f, 0.f, 0.f, 0.f);
    float4 a1 = make_float4(0.f, 0.f, 0.f, 0.f);
    for (; i < end; i++) {
        int2 ev = d_sorted[i];
        float w = __int_as_float(ev.y);
        const float* src = d_out0 + (size_t)ev.x * 256;
        float4 f0 = *(const float4*)(src + lane * 4);
        float4 f1 = *(const float4*)(src + 128 + lane * 4);
        a0.x = fmaf(w, f0.x, a0.x); a0.y = fmaf(w, f0.y, a0.y);
        a0.z = fmaf(w, f0.z, a0.z); a0.w = fmaf(w, f0.w, a0.w);
        a1.x = fmaf(w, f1.x, a1.x); a1.y = fmaf(w, f1.y, a1.y);
        a1.z = fmaf(w, f1.z, a1.z); a1.w = fmaf(w, f1.w, a1.w);
    }
    float di = d_deginv[v];
    a0.x *= di; a0.y *= di; a0.z *= di; a0.w *= di;
    a1.x *= di; a1.y *= di; a1.z *= di; a1.w *= di;
    *(float4*)(d_z1 + (size_t)v * 256 + lane * 4)       = a0;
    *(float4*)(d_z1 + (size_t)v * 256 + 128 + lane * 4) = a1;
}

// ---------------- tensor-core concat-GEMM via mma.sync (bf16 hi/lo compensated) ----------------
template <int NC, bool L0F>
__global__ void __launch_bounds__(256) k_gemm_mma(const float* __restrict__ xin,
                                                  const float* __restrict__ bias) {
    extern __shared__ unsigned char sm[];
    const int SBOFF = 1024;
    const int SAOFF = 1024 + NC * 36864;
    int tid = threadIdx.x;
    int wid = tid >> 5;
    int lane = tid & 31;
    int tile = blockIdx.x;
    int wm = (wid & 3) * 32;
    int wn = (wid >> 2) * 64;

    // copy B image + bias
    {
        const uint4* bsrc = L0F ? d_Bimg0 : d_Bimg1;
        uint4* bdst = (uint4*)(sm + SBOFF);
        for (int i = tid; i < NC * 2304; i += 256) bdst[i] = bsrc[i];
        if (tid < 128) ((float*)sm)[tid] = bias[tid];
    }

    // A chunk loader: 128 rows x 64 k fp32 -> bf16 hi/lo padded tile
    int arow = tid >> 1;
    int kq = (tid & 1) * 32;
    int row = tile * 128 + arow;
    bool ok = row < NROWS;
    auto loadA = [&](int c, int stage) {
        const float* src;
        if (L0F) src = (c == 0) ? (xin + ((size_t)(row & 1) * NV + (row >> 1)) * 64)
                                : (d_z0 + (size_t)row * 64);
        else     src = (c < 2) ? (d_out0 + (size_t)row * 128 + c * 64)
                               : (d_z1 + (size_t)row * 128 + (c - 2) * 64);
        unsigned short* ahi = (unsigned short*)(sm + SAOFF + stage * 36864);
        unsigned short* alo = ahi + 128 * BST;
#pragma unroll
        for (int j = 0; j < 8; j++) {
            int kk = kq + j * 4;
            float4 v = ok ? *(const float4*)(src + kk) : make_float4(0.f, 0.f, 0.f, 0.f);
            uint32_t h0 = (uint32_t)bfb(v.x) | ((uint32_t)bfb(v.y) << 16);
            uint32_t h1 = (uint32_t)bfb(v.z) | ((uint32_t)bfb(v.w) << 16);
            uint32_t l0 = (uint32_t)bfb(v.x - bfhi(v.x)) | ((uint32_t)bfb(v.y - bfhi(v.y)) << 16);
            uint32_t l1 = (uint32_t)bfb(v.z - bfhi(v.z)) | ((uint32_t)bfb(v.w - bfhi(v.w)) << 16);
            *(uint2*)(ahi + arow * BST + kk) = make_uint2(h0, h1);
            *(uint2*)(alo + arow * BST + kk) = make_uint2(l0, l1);
        }
    };

    float acc[2][8][4];
#pragma unroll
    for (int m = 0; m < 2; m++)
#pragma unroll
        for (int nf = 0; nf < 8; nf++)
#pragma unroll
            for (int q = 0; q < 4; q++) acc[m][nf][q] = 0.f;

    uint32_t smb = smem_u32(sm);
    int a_r = wm + (lane & 15);
    int a_k = (lane >> 4) << 3;
    int b_n = wn + (lane & 7) + ((lane >> 4) << 3);
    int b_k = ((lane >> 3) & 1) << 3;

    auto compute = [&](int c, int stage) {
        uint32_t ahiB = smb + SAOFF + stage * 36864;
        uint32_t bhiB = smb + SBOFF + c * 36864;
#pragma unroll
        for (int ks = 0; ks < 4; ks++) {
            int k0 = ks * 16;
            uint32_t ahi[2][4], alo[2][4];
#pragma unroll
            for (int m = 0; m < 2; m++) {
                uint32_t ad = ahiB + (uint32_t)(((a_r + m * 16) * BST + k0 + a_k) * 2);
                ldmat4(ahi[m], ad);
                ldmat4(alo[m], ad + 128 * BST * 2);
            }
            uint32_t bhi[8][2], blo[8][2];
#pragma unroll
            for (int g = 0; g < 4; g++) {
                uint32_t bd = bhiB + (uint32_t)((((b_n + g * 16) * BST) + k0 + b_k) * 2);
                uint32_t t[4];
                ldmat4(t, bd);
                bhi[2 * g][0] = t[0]; bhi[2 * g][1] = t[1];
                bhi[2 * g + 1][0] = t[2]; bhi[2 * g + 1][1] = t[3];
                ldmat4(t, bd + 128 * BST * 2);
                blo[2 * g][0] = t[0]; blo[2 * g][1] = t[1];
                blo[2 * g + 1][0] = t[2]; blo[2 * g + 1][1] = t[3];
            }
#pragma unroll
            for (int m = 0; m < 2; m++)
#pragma unroll
                for (int nf = 0; nf < 8; nf++) {
                    mma_bf16(acc[m][nf], ahi[m], bhi[nf]);
                    mma_bf16(acc[m][nf], alo[m], bhi[nf]);
                    mma_bf16(acc[m][nf], ahi[m], blo[nf]);
                }
        }
    };

    loadA(0, 0);
    __syncthreads();
#pragma unroll
    for (int c = 0; c < NC; c++) {
        if (c + 1 < NC) loadA(c + 1, (c + 1) & 1);
        compute(c, c & 1);
        __syncthreads();
    }

    // epilogue
    float* outp = L0F ? d_out0 : d_out1;
    const float* sbias = (const float*)sm;
#pragma unroll
    for (int m = 0; m < 2; m++) {
        int r0 = tile * 128 + wm + m * 16 + (lane >> 2);
#pragma unroll
        for (int nf = 0; nf < 8; nf++) {
            int col = wn + nf * 8 + (lane & 3) * 2;
            float bx = sbias[col], by = sbias[col + 1];
            float o0 = acc[m][nf][0] + bx, o1 = acc[m][nf][1] + by;
            float o2 = acc[m][nf][2] + bx, o3 = acc[m][nf][3] + by;
            if (L0F) {
                o0 = (o0 >= 0.f) ? o0 : 0.2f * o0;
                o1 = (o1 >= 0.f) ? o1 : 0.2f * o1;
                o2 = (o2 >= 0.f) ? o2 : 0.2f * o2;
                o3 = (o3 >= 0.f) ? o3 : 0.2f * o3;
            }
            if (r0 < NROWS)     *(float2*)(outp + (size_t)r0 * 128 + col)       = make_float2(o0, o1);
            if (r0 + 8 < NROWS) *(float2*)(outp + (size_t)(r0 + 8) * 128 + col) = make_float2(o2, o3);
        }
    }
}

// ---------------- final: pool(out1) + (pool(x) @ W_res + sw * b_res) ----------------
__global__ void __launch_bounds__(256) k_final(const float* __restrict__ x,
                                               const int* __restrict__ asgnIdx,
                                               const float* __restrict__ asgnVal,
                                               const float* __restrict__ Wres,
                                               const float* __restrict__ bres,
                                               float* __restrict__ out) {
    __shared__ float xps[4][64];
    int sub = threadIdx.x >> 6;
    int p = threadIdx.x & 63;
    int r = blockIdx.x * 4 + sub;
    bool ok = r < 2 * CN;
    int c = r >> 1, b = r & 1;
    const int* fine = asgnIdx + NV;
    float sw = 0.f;
    float2 p1 = make_float2(0.f, 0.f);
    if (ok) {
        int i0 = 4 * c;
        float a = 0.f;
#pragma unroll
        for (int j = 0; j < 4; j++) {
            int f = fine[i0 + j];
            float w = asgnVal[i0 + j];
            a = fmaf(w, x[((size_t)b * NV + f) * 64 + p], a);
            sw += w;
            float2 o1 = *(const float2*)(&d_out1[(size_t)f * 256 + b * 128 + 2 * p]);
            p1.x = fmaf(w, o1.x, p1.x);
            p1.y = fmaf(w, o1.y, p1.y);
        }
        xps[sub][p] = a;
    }
    __syncthreads();
    if (ok) {
        float2 br = *(const float2*)(bres + 2 * p);
        float accx = p1.x + sw * br.x;
        float accy = p1.y + sw * br.y;
#pragma unroll 8
        for (int k = 0; k < 64; k++) {
            float xk = xps[sub][k];
            float2 w2 = *(const float2*)(Wres + k * 128 + 2 * p);
            accx = fmaf(xk, w2.x, accx);
            accy = fmaf(xk, w2.y, accy);
        }
        *(float2*)(out + ((size_t)b * CN + c) * 128 + 2 * p) = make_float2(accx, accy);
    }
}

// ---------------- launch ----------------
extern "C" void kernel_launch(void* const* d_in, const int* in_sizes, int n_in,
                              void* d_out, int out_size) {
    const float* x       = (const float*)d_in[0];
    const float* adjVal  = (const float*)d_in[1];
    const float* edgeOne = (const float*)d_in[2];
    const int*   E_start = (const int*)d_in[3];
    const int*   E_end   = (const int*)d_in[4];
    const int*   asgnIdx = (const int*)d_in[5];
    const float* asgnVal = (const float*)d_in[6];
    const float* W_res   = (const float*)d_in[7];
    const float* b_res   = (const float*)d_in[8];
    const float* W0s     = (const float*)d_in[9];
    const float* W0n     = (const float*)d_in[10];
    const float* b0      = (const float*)d_in[11];
    const float* W1s     = (const float*)d_in[12];
    const float* W1n     = (const float*)d_in[13];
    const float* b1      = (const float*)d_in[14];
    float* out = (float*)d_out;

    const int smA = 1024 + 2 * 36864 + 2 * 36864;   // 148480
    const int smB = 1024 + 4 * 36864 + 2 * 36864;   // 222208
    cudaFuncSetAttribute(k_gemm_mma<2, true>,  cudaFuncAttributeMaxDynamicSharedMemorySize, smA);
    cudaFuncSetAttribute(k_gemm_mma<4, false>, cudaFuncAttributeMaxDynamicSharedMemorySize, smB);

    k_init<<<64, 256>>>(W0s, W0n, W1s, W1n);                       // 0
    k_preproc<<<PPB, 512>>>(E_start, E_end, adjVal, edgeOne);      // 1
    k_gather64<<<NV / 8, 256>>>(x);                                // 2
    k_gemm_mma<2, true><<<NTILES, 256, smA>>>(x, b0);              // 3 <- ncu capture slot
    k_gather128<<<NV / 8, 256>>>();                                // 4
    k_gemm_mma<4, false><<<NTILES, 256, smB>>>(x, b1);             // 5
    k_final<<<(2 * CN + 3) / 4, 256>>>(x, asgnIdx, asgnVal, W_res, b_res, out); // 6
}

// round 6
// speedup vs baseline: 1.7377x; 1.7377x over previous
#include <cuda_runtime.h>
#include <cuda_bf16.h>
#include <cstdint>

#define NV 50000
#define NE 400000
#define CN 12500
#define NROWS 100000
#define NTILES 782      /* ceil(100000/128) */
#define BST 72          /* bf16 elems per smem row (64 data + 8 pad) */
#define SFB 98          /* scanfill blocks */

typedef unsigned long long ull;

// ---------------- scratch (static device memory) ----------------
__device__ int   d_bar;
__device__ int   d_degcnt[NV];
__device__ float d_degF[NV];
__device__ int   d_rowptr[NV + 1];
__device__ int   d_cursor[NV];
__device__ float d_deginv[NV];
__device__ int   d_blocksums[128];
__device__ int2  d_sorted[NE];              // (end, val bits)
__device__ float d_z0[(size_t)NV * 128];    // [v][b*64+k]
__device__ float d_out0[(size_t)NV * 256];  // row (2v+b) * 128
__device__ float d_z1[(size_t)NV * 256];
__device__ float d_out1[(size_t)NV * 256];
// Pre-converted bf16 weight images, per-chunk contiguous 36864B: hi block (128n x BST), lo block
__device__ uint4 d_Bimg0[(2 * 36864) / 16];   // L0: 2 chunks
__device__ uint4 d_Bimg1[(4 * 36864) / 16];   // L1: 4 chunks

// ---------------- helpers ----------------
__device__ __forceinline__ uint32_t smem_u32(const void* p) {
    uint32_t a;
    asm("{ .reg .u64 t; cvta.to.shared.u64 t, %1; cvt.u32.u64 %0, t; }" : "=r"(a) : "l"(p));
    return a;
}
__device__ __forceinline__ void ldmat4(uint32_t* r, uint32_t addr) {
    asm volatile("ldmatrix.sync.aligned.m8n8.x4.shared.b16 {%0,%1,%2,%3}, [%4];"
                 : "=r"(r[0]), "=r"(r[1]), "=r"(r[2]), "=r"(r[3]) : "r"(addr));
}
__device__ __forceinline__ void mma_bf16(float* d, const uint32_t* a, const uint32_t* b) {
    asm volatile("mma.sync.aligned.m16n8k16.row.col.f32.bf16.bf16.f32 "
                 "{%0,%1,%2,%3}, {%4,%5,%6,%7}, {%8,%9}, {%0,%1,%2,%3};"
                 : "+f"(d[0]), "+f"(d[1]), "+f"(d[2]), "+f"(d[3])
                 : "r"(a[0]), "r"(a[1]), "r"(a[2]), "r"(a[3]), "r"(b[0]), "r"(b[1]));
}
__device__ __forceinline__ void cpa16(uint32_t dst, const void* src) {
    asm volatile("cp.async.cg.shared.global [%0], [%1], 16;" :: "r"(dst), "l"(src) : "memory");
}
#define CPA_COMMIT() asm volatile("cp.async.commit_group;" ::: "memory")
#define CPA_WAIT0()  asm volatile("cp.async.wait_group 0;" ::: "memory")

__device__ __forceinline__ float bfhi(float x) {
    return __bfloat162float(__float2bfloat16(x));
}
__device__ __forceinline__ unsigned short bfb(float x) {
    return __bfloat16_as_ushort(__float2bfloat16(x));
}

// software grid barrier (SFB blocks co-resident by construction)
__device__ __forceinline__ void gbar(int target) {
    __syncthreads();
    __threadfence();
    if (threadIdx.x == 0) {
        atomicAdd(&d_bar, 1);
        while (atomicAdd(&d_bar, 0) < target) { }
    }
    __syncthreads();
    __threadfence();
}

// ---------------- k_prep: zero scratch + build bf16 hi/lo weight images ----------------
__global__ void k_prep(const float* __restrict__ W0s, const float* __restrict__ W0n,
                       const float* __restrict__ W1s, const float* __restrict__ W1n) {
    int gt = blockIdx.x * blockDim.x + threadIdx.x;
    int stride = gridDim.x * blockDim.x;
    if (gt == 0) d_bar = 0;
    for (int i = gt; i < NV; i += stride) {
        d_degcnt[i] = 0; d_degF[i] = 0.f; d_cursor[i] = 0;
    }
    // items: L0 = 2 chunks * 128 n * 64 k = 16384; L1 = 32768
    for (int it = gt; it < 49152; it += stride) {
        bool isL1 = it >= 16384;
        int loc = isL1 ? (it - 16384) : it;
        int c = loc >> 13;
        int rem = loc & 8191;
        int n = rem >> 6;
        int kk = rem & 63;
        int k = c * 64 + kk;
        int KH = isL1 ? 128 : 64;
        const float* W;
        if (isL1) W = (k < KH) ? W1s : (W1n - (size_t)KH * 128);
        else      W = (k < KH) ? W0s : (W0n - (size_t)KH * 128);
        float v = W[(size_t)k * 128 + n];
        float hi = bfhi(v);
        unsigned short* img = isL1 ? (unsigned short*)d_Bimg1 : (unsigned short*)d_Bimg0;
        img[((size_t)(c * 2 + 0) * 128 + n) * BST + kk] = bfb(v);
        img[((size_t)(c * 2 + 1) * 128 + n) * BST + kk] = bfb(v - hi);
    }
}

// ---------------- k_hist ----------------
__global__ void k_hist(const int* __restrict__ Es, const float* __restrict__ one) {
    int e = blockIdx.x * blockDim.x + threadIdx.x;
    if (e < NE) {
        int s = Es[e];
        atomicAdd(&d_degcnt[s], 1);
        atomicAdd(&d_degF[s], one[e]);
    }
}

// ---------------- k_scanfill: scan -> fixup -> CSR fill (grid barriers) ----------------
__global__ void __launch_bounds__(512) k_scanfill(const int* __restrict__ Es,
                                                  const int* __restrict__ Ee,
                                                  const float* __restrict__ adj) {
    __shared__ int s[512];
    const int NT = SFB * 512;
    int tid = threadIdx.x;
    int gt = blockIdx.x * 512 + tid;

    // phase 0: per-block inclusive scan of degcnt
    int val = (gt < NV) ? d_degcnt[gt] : 0;
    s[tid] = val;
    __syncthreads();
    for (int off = 1; off < 512; off <<= 1) {
        int t = (tid >= off) ? s[tid - off] : 0;
        __syncthreads();
        s[tid] += t;
        __syncthreads();
    }
    if (gt < NV) d_rowptr[gt + 1] = s[tid];
    if (tid == 511) d_blocksums[blockIdx.x] = s[511];
    gbar(SFB);

    // phase 1: redundant scan of block sums + fixup + deginv
    {
        s[tid] = (tid < SFB) ? d_blocksums[tid] : 0;
        __syncthreads();
        for (int off = 1; off < 512; off <<= 1) {
            int u = (tid >= off) ? s[tid - off] : 0;
            __syncthreads();
            s[tid] += u;
            __syncthreads();
        }
        int boff = (blockIdx.x > 0) ? s[blockIdx.x - 1] : 0;
        if (gt < NV) {
            d_rowptr[gt + 1] += boff;
            d_deginv[gt] = 1.0f / fmaxf(d_degF[gt], 1.0f);
        }
        if (gt == 0) d_rowptr[0] = 0;
    }
    gbar(2 * SFB);

    // phase 2: CSR fill
    for (int e = gt; e < NE; e += NT) {
        int src = Es[e];
        int p = atomicAdd(&d_cursor[src], 1);
        d_sorted[d_rowptr[src] + p] = make_int2(Ee[e], __float_as_int(adj[e]));
    }
}

// ---------------- aggregation: warp per node, float4 per lane, unroll-2 ----------------
__global__ void __launch_bounds__(256) k_gather64(const float* __restrict__ x) {
    int v = blockIdx.x * 8 + (threadIdx.x >> 5);
    int lane = threadIdx.x & 31;
    int b = lane >> 4, k = (lane & 15) * 4;
    const float* xb = x + ((size_t)b * NV) * 64 + k;
    int i = d_rowptr[v], end = d_rowptr[v + 1];
    float4 acc = make_float4(0.f, 0.f, 0.f, 0.f);
    for (; i + 2 <= end; i += 2) {
        int2 e0 = d_sorted[i];
        int2 e1 = d_sorted[i + 1];
        float w0 = __int_as_float(e0.y), w1 = __int_as_float(e1.y);
        float4 f0 = *(const float4*)(xb + (size_t)e0.x * 64);
        float4 f1 = *(const float4*)(xb + (size_t)e1.x * 64);
        acc.x = fmaf(w0, f0.x, fmaf(w1, f1.x, acc.x));
        acc.y = fmaf(w0, f0.y, fmaf(w1, f1.y, acc.y));
        acc.z = fmaf(w0, f0.z, fmaf(w1, f1.z, acc.z));
        acc.w = fmaf(w0, f0.w, fmaf(w1, f1.w, acc.w));
    }
    if (i < end) {
        int2 e0 = d_sorted[i];
        float w0 = __int_as_float(e0.y);
        float4 f0 = *(const float4*)(xb + (size_t)e0.x * 64);
        acc.x = fmaf(w0, f0.x, acc.x);
        acc.y = fmaf(w0, f0.y, acc.y);
        acc.z = fmaf(w0, f0.z, acc.z);
        acc.w = fmaf(w0, f0.w, acc.w);
    }
    float di = d_deginv[v];
    acc.x *= di; acc.y *= di; acc.z *= di; acc.w *= di;
    *(float4*)(d_z0 + (size_t)v * 128 + lane * 4) = acc;
}

__global__ void __launch_bounds__(256) k_gather128() {
    int v = blockIdx.x * 8 + (threadIdx.x >> 5);
    int lane = threadIdx.x & 31;
    int i = d_rowptr[v], end = d_rowptr[v + 1];
    float4 a0 = make_float4(0.f, 0.f, 0.f, 0.f);
    float4 a1 = make_float4(0.f, 0.f, 0.f, 0.f);
    for (; i + 2 <= end; i += 2) {
        int2 e0 = d_sorted[i];
        int2 e1 = d_sorted[i + 1];
        float w0 = __int_as_float(e0.y), w1 = __int_as_float(e1.y);
        const float* s0 = d_out0 + (size_t)e0.x * 256 + lane * 4;
        const float* s1 = d_out0 + (size_t)e1.x * 256 + lane * 4;
        float4 f0 = *(const float4*)(s0);
        float4 g0 = *(const float4*)(s0 + 128);
        float4 f1 = *(const float4*)(s1);
        float4 g1 = *(const float4*)(s1 + 128);
        a0.x = fmaf(w0, f0.x, fmaf(w1, f1.x, a0.x));
        a0.y = fmaf(w0, f0.y, fmaf(w1, f1.y, a0.y));
        a0.z = fmaf(w0, f0.z, fmaf(w1, f1.z, a0.z));
        a0.w = fmaf(w0, f0.w, fmaf(w1, f1.w, a0.w));
        a1.x = fmaf(w0, g0.x, fmaf(w1, g1.x, a1.x));
        a1.y = fmaf(w0, g0.y, fmaf(w1, g1.y, a1.y));
        a1.z = fmaf(w0, g0.z, fmaf(w1, g1.z, a1.z));
        a1.w = fmaf(w0, g0.w, fmaf(w1, g1.w, a1.w));
    }
    if (i < end) {
        int2 e0 = d_sorted[i];
        float w0 = __int_as_float(e0.y);
        const float* s0 = d_out0 + (size_t)e0.x * 256 + lane * 4;
        float4 f0 = *(const float4*)(s0);
        float4 g0 = *(const float4*)(s0 + 128);
        a0.x = fmaf(w0, f0.x, a0.x); a0.y = fmaf(w0, f0.y, a0.y);
        a0.z = fmaf(w0, f0.z, a0.z); a0.w = fmaf(w0, f0.w, a0.w);
        a1.x = fmaf(w0, g0.x, a1.x); a1.y = fmaf(w0, g0.y, a1.y);
        a1.z = fmaf(w0, g0.z, a1.z); a1.w = fmaf(w0, g0.w, a1.w);
    }
    float di = d_deginv[v];
    a0.x *= di; a0.y *= di; a0.z *= di; a0.w *= di;
    a1.x *= di; a1.y *= di; a1.z *= di; a1.w *= di;
    *(float4*)(d_z1 + (size_t)v * 256 + lane * 4)       = a0;
    *(float4*)(d_z1 + (size_t)v * 256 + 128 + lane * 4) = a1;
}

// ---------------- tensor-core concat-GEMM via mma.sync (bf16 hi/lo compensated) ----------------
// CTA: 128 rows x 128 cols, 256 threads = 8 warps (4m x 2n), warp tile 32x64.
// smem (109 KB -> 2 CTAs/SM): [0,512) bias; [1024) A buf (hi+lo, 36864B);
// then B chunk double-buffer 2 x 36864B streamed via cp.async.
template <int NC, bool L0F>
__global__ void __launch_bounds__(256, 2) k_gemm_mma(const float* __restrict__ xin,
                                                     const float* __restrict__ bias) {
    extern __shared__ unsigned char sm[];
    const int SA = 1024;
    const int SB = 1024 + 36864;
    int tid = threadIdx.x;
    int wid = tid >> 5;
    int lane = tid & 31;
    int tile = blockIdx.x;
    int wm = (wid & 3) * 32;
    int wn = (wid >> 2) * 64;
    uint32_t smb = smem_u32(sm);

    const unsigned char* bimg = L0F ? (const unsigned char*)d_Bimg0 : (const unsigned char*)d_Bimg1;
    auto prefetchB = [&](int c, int stage) {
        const unsigned char* src = bimg + (size_t)c * 36864 + tid * 16;
        uint32_t dst = smb + SB + stage * 36864 + tid * 16;
#pragma unroll
        for (int i = 0; i < 9; i++) cpa16(dst + i * 4096, src + i * 4096);
        CPA_COMMIT();
    };

    if (tid < 128) ((float*)sm)[tid] = bias[tid];

    // A chunk loader: 128 rows x 64 k fp32 -> bf16 hi/lo padded tile (single buffer)
    int arow = tid >> 1;
    int kq = (tid & 1) * 32;
    int row = tile * 128 + arow;
    bool ok = row < NROWS;
    auto loadA = [&](int c) {
        const float* src;
        if (L0F) src = (c == 0) ? (xin + ((size_t)(row & 1) * NV + (row >> 1)) * 64)
                                : (d_z0 + (size_t)row * 64);
        else     src = (c < 2) ? (d_out0 + (size_t)row * 128 + c * 64)
                               : (d_z1 + (size_t)row * 128 + (c - 2) * 64);
        unsigned short* ahi = (unsigned short*)(sm + SA);
        unsigned short* alo = ahi + 128 * BST;
#pragma unroll
        for (int j = 0; j < 8; j++) {
            int kk = kq + j * 4;
            float4 v = ok ? *(const float4*)(src + kk) : make_float4(0.f, 0.f, 0.f, 0.f);
            uint32_t h0 = (uint32_t)bfb(v.x) | ((uint32_t)bfb(v.y) << 16);
            uint32_t h1 = (uint32_t)bfb(v.z) | ((uint32_t)bfb(v.w) << 16);
            uint32_t l0 = (uint32_t)bfb(v.x - bfhi(v.x)) | ((uint32_t)bfb(v.y - bfhi(v.y)) << 16);
            uint32_t l1 = (uint32_t)bfb(v.z - bfhi(v.z)) | ((uint32_t)bfb(v.w - bfhi(v.w)) << 16);
            *(uint2*)(ahi + arow * BST + kk) = make_uint2(h0, h1);
            *(uint2*)(alo + arow * BST + kk) = make_uint2(l0, l1);
        }
    };

    float acc[2][8][4];
#pragma unroll
    for (int m = 0; m < 2; m++)
#pragma unroll
        for (int nf = 0; nf < 8; nf++)
#pragma unroll
            for (int q = 0; q < 4; q++) acc[m][nf][q] = 0.f;

    int a_r = wm + (lane & 15);
    int a_k = (lane >> 4) << 3;
    int b_n = wn + (lane & 7) + ((lane >> 4) << 3);
    int b_k = ((lane >> 3) & 1) << 3;

    auto compute = [&](int stage) {
        uint32_t ahiB = smb + SA;
        uint32_t bhiB = smb + SB + stage * 36864;
#pragma unroll
        for (int ks = 0; ks < 4; ks++) {
            int k0 = ks * 16;
            uint32_t ahi[2][4], alo[2][4];
#pragma unroll
            for (int m = 0; m < 2; m++) {
                uint32_t ad = ahiB + (uint32_t)(((a_r + m * 16) * BST + k0 + a_k) * 2);
                ldmat4(ahi[m], ad);
                ldmat4(alo[m], ad + 128 * BST * 2);
            }
            uint32_t bhi[8][2], blo[8][2];
#pragma unroll
            for (int g = 0; g < 4; g++) {
                uint32_t bd = bhiB + (uint32_t)((((b_n + g * 16) * BST) + k0 + b_k) * 2);
                uint32_t t[4];
                ldmat4(t, bd);
                bhi[2 * g][0] = t[0]; bhi[2 * g][1] = t[1];
                bhi[2 * g + 1][0] = t[2]; bhi[2 * g + 1][1] = t[3];
                ldmat4(t, bd + 128 * BST * 2);
                blo[2 * g][0] = t[0]; blo[2 * g][1] = t[1];
                blo[2 * g + 1][0] = t[2]; blo[2 * g + 1][1] = t[3];
            }
#pragma unroll
            for (int m = 0; m < 2; m++)
#pragma unroll
                for (int nf = 0; nf < 8; nf++) {
                    mma_bf16(acc[m][nf], ahi[m], bhi[nf]);
                    mma_bf16(acc[m][nf], alo[m], bhi[nf]);
                    mma_bf16(acc[m][nf], ahi[m], blo[nf]);
                }
        }
    };

    prefetchB(0, 0);
    loadA(0);
    CPA_WAIT0();
    __syncthreads();
#pragma unroll
    for (int c = 0; c < NC; c++) {
        if (c + 1 < NC) prefetchB(c + 1, (c + 1) & 1);
        compute(c & 1);
        __syncthreads();
        if (c + 1 < NC) {
            loadA(c + 1);
            CPA_WAIT0();
            __syncthreads();
        }
    }

    // epilogue
    float* outp = L0F ? d_out0 : d_out1;
    const float* sbias = (const float*)sm;
#pragma unroll
    for (int m = 0; m < 2; m++) {
        int r0 = tile * 128 + wm + m * 16 + (lane >> 2);
#pragma unroll
        for (int nf = 0; nf < 8; nf++) {
            int col = wn + nf * 8 + (lane & 3) * 2;
            float bx = sbias[col], by = sbias[col + 1];
            float o0 = acc[m][nf][0] + bx, o1 = acc[m][nf][1] + by;
            float o2 = acc[m][nf][2] + bx, o3 = acc[m][nf][3] + by;
            if (L0F) {
                o0 = (o0 >= 0.f) ? o0 : 0.2f * o0;
                o1 = (o1 >= 0.f) ? o1 : 0.2f * o1;
                o2 = (o2 >= 0.f) ? o2 : 0.2f * o2;
                o3 = (o3 >= 0.f) ? o3 : 0.2f * o3;
            }
            if (r0 < NROWS)     *(float2*)(outp + (size_t)r0 * 128 + col)       = make_float2(o0, o1);
            if (r0 + 8 < NROWS) *(float2*)(outp + (size_t)(r0 + 8) * 128 + col) = make_float2(o2, o3);
        }
    }
}

// ---------------- final: pool(out1) + (pool(x) @ W_res + sw * b_res) ----------------
__global__ void __launch_bounds__(256) k_final(const float* __restrict__ x,
                                               const int* __restrict__ asgnIdx,
                                               const float* __restrict__ asgnVal,
                                               const float* __restrict__ Wres,
                                               const float* __restrict__ bres,
                                               float* __restrict__ out) {
    __shared__ float xps[4][64];
    int sub = threadIdx.x >> 6;
    int p = threadIdx.x & 63;
    int r = blockIdx.x * 4 + sub;
    bool ok = r < 2 * CN;
    int c = r >> 1, b = r & 1;
    const int* fine = asgnIdx + NV;
    float sw = 0.f;
    float2 p1 = make_float2(0.f, 0.f);
    if (ok) {
        int i0 = 4 * c;
        float a = 0.f;
#pragma unroll
        for (int j = 0; j < 4; j++) {
            int f = fine[i0 + j];
            float w = asgnVal[i0 + j];
            a = fmaf(w, x[((size_t)b * NV + f) * 64 + p], a);
            sw += w;
            float2 o1 = *(const float2*)(&d_out1[(size_t)f * 256 + b * 128 + 2 * p]);
            p1.x = fmaf(w, o1.x, p1.x);
            p1.y = fmaf(w, o1.y, p1.y);
        }
        xps[sub][p] = a;
    }
    __syncthreads();
    if (ok) {
        float2 br = *(const float2*)(bres + 2 * p);
        float accx = p1.x + sw * br.x;
        float accy = p1.y + sw * br.y;
#pragma unroll 8
        for (int k = 0; k < 64; k++) {
            float xk = xps[sub][k];
            float2 w2 = *(const float2*)(Wres + k * 128 + 2 * p);
            accx = fmaf(xk, w2.x, accx);
            accy = fmaf(xk, w2.y, accy);
        }
        *(float2*)(out + ((size_t)b * CN + c) * 128 + 2 * p) = make_float2(accx, accy);
    }
}

// ---------------- launch ----------------
extern "C" void kernel_launch(void* const* d_in, const int* in_sizes, int n_in,
                              void* d_out, int out_size) {
    const float* x       = (const float*)d_in[0];
    const float* adjVal  = (const float*)d_in[1];
    const float* edgeOne = (const float*)d_in[2];
    const int*   E_start = (const int*)d_in[3];
    const int*   E_end   = (const int*)d_in[4];
    const int*   asgnIdx = (const int*)d_in[5];
    const float* asgnVal = (const float*)d_in[6];
    const float* W_res   = (const float*)d_in[7];
    const float* b_res   = (const float*)d_in[8];
    const float* W0s     = (const float*)d_in[9];
    const float* W0n     = (const float*)d_in[10];
    const float* b0      = (const float*)d_in[11];
    const float* W1s     = (const float*)d_in[12];
    const float* W1n     = (const float*)d_in[13];
    const float* b1      = (const float*)d_in[14];
    float* out = (float*)d_out;

    const int smG = 1024 + 3 * 36864;   // 111616 -> 2 CTAs/SM
    cudaFuncSetAttribute(k_gemm_mma<2, true>,  cudaFuncAttributeMaxDynamicSharedMemorySize, smG);
    cudaFuncSetAttribute(k_gemm_mma<4, false>, cudaFuncAttributeMaxDynamicSharedMemorySize, smG);

    k_prep<<<64, 256>>>(W0s, W0n, W1s, W1n);                       // 0
    k_hist<<<(NE + 255) / 256, 256>>>(E_start, edgeOne);           // 1
    k_scanfill<<<SFB, 512>>>(E_start, E_end, adjVal);              // 2
    k_gather64<<<NV / 8, 256>>>(x);                                // 3 <- ncu capture slot
    k_gemm_mma<2, true><<<NTILES, 256, smG>>>(x, b0);              // 4
    k_gather128<<<NV / 8, 256>>>();                                // 5
    k_gemm_mma<4, false><<<NTILES, 256, smG>>>(x, b1);             // 6
    k_final<<<(2 * CN + 3) / 4, 256>>>(x, asgnIdx, asgnVal, W_res, b_res, out); // 7
}